// round 8
// baseline (speedup 1.0000x reference)
#include <cuda_runtime.h>
#include <cuda_fp16.h>
#include <math.h>
#include <stdint.h>

#define D_MODEL 2048
#define NH      16
#define DK      128
#define SEQ     2048
#define BATCH   2
#define KDIM    2048
#define MDIM    (BATCH*SEQ)   // 4096

// -------- scratch (static device memory; no cudaMalloc allowed) ------------
__device__ __half g_Q  [BATCH*NH*SEQ*DK];     // [b,h,s,d] post-RoPE, pre-scaled
__device__ __half g_K  [BATCH*NH*SEQ*DK];     // [b,h,s,d] post-RoPE
__device__ __half g_Vt [BATCH*NH*DK*SEQ];     // [b,h,d,s] transposed
__device__ __half g_att[BATCH*SEQ*D_MODEL];   // [b,s,h*128+d]
__device__ __half g_xh [MDIM*KDIM];           // fp16 x
__device__ __half g_wqh[KDIM*KDIM];
__device__ __half g_wkh[KDIM*KDIM];
__device__ __half g_wvh[KDIM*KDIM];
__device__ __half g_woh[KDIM*KDIM];
__device__ float  g_rc [SEQ*64];              // RoPE cos LUT [s][d/2]
__device__ float  g_rs [SEQ*64];              // RoPE sin LUT

// ============================================================================
// helpers
// ============================================================================
__device__ __forceinline__ uint32_t smem_u32(const void* p) {
    uint32_t a;
    asm("{ .reg .u64 t; cvta.to.shared.u64 t, %1; cvt.u32.u64 %0, t; }"
        : "=r"(a) : "l"(p));
    return a;
}

#define CP16(dst, src) \
    asm volatile("cp.async.cg.shared.global [%0], [%1], 16;" \
                 :: "r"(dst), "l"(src) : "memory")
#define CP_COMMIT()  asm volatile("cp.async.commit_group;" ::: "memory")
#define CP_WAIT(n)   asm volatile("cp.async.wait_group %0;" :: "n"(n) : "memory")

__device__ __forceinline__ void mma_f16(float& d0, float& d1, float& d2, float& d3,
                                        uint32_t a0, uint32_t a1, uint32_t a2, uint32_t a3,
                                        uint32_t b0, uint32_t b1) {
    asm volatile(
        "mma.sync.aligned.m16n8k16.row.col.f32.f16.f16.f32 "
        "{%0,%1,%2,%3}, {%4,%5,%6,%7}, {%8,%9}, {%0,%1,%2,%3};"
        : "+f"(d0), "+f"(d1), "+f"(d2), "+f"(d3)
        : "r"(a0), "r"(a1), "r"(a2), "r"(a3), "r"(b0), "r"(b1));
}

// ============================================================================
// prep: all five fp32 -> fp16 conversions in ONE launch. 8 elems/thread.
// Element space: [0, 8M) = x ; [8M, 24M) = wq|wk|wv|wo (4M each).
// ============================================================================
#define XELEMS  ((size_t)MDIM * KDIM)          // 8M
#define WELEMS  ((size_t)KDIM * KDIM)          // 4M

__global__ void to_half_all(const float* __restrict__ x,
                            const float* __restrict__ wq,
                            const float* __restrict__ wk,
                            const float* __restrict__ wv,
                            const float* __restrict__ wo)
{
    size_t e = ((size_t)blockIdx.x * blockDim.x + threadIdx.x) * 8;
    const float* src;
    __half* dst;
    size_t off;
    if (e < XELEMS) { src = x; dst = g_xh; off = e; }
    else {
        size_t j = e - XELEMS;
        int w = (int)(j / WELEMS);
        off = j - (size_t)w * WELEMS;
        src = (w == 0) ? wq : (w == 1) ? wk : (w == 2) ? wv : wo;
        dst = (w == 0) ? g_wqh : (w == 1) ? g_wkh : (w == 2) ? g_wvh : g_woh;
    }
    float4 v0 = *(const float4*)&src[off];
    float4 v1 = *(const float4*)&src[off + 4];
    __half2 h[4];
    h[0] = __floats2half2_rn(v0.x, v0.y);
    h[1] = __floats2half2_rn(v0.z, v0.w);
    h[2] = __floats2half2_rn(v1.x, v1.y);
    h[3] = __floats2half2_rn(v1.z, v1.w);
    *(uint4*)&dst[off] = *(uint4*)h;
}

// ============================================================================
// prep: RoPE cos/sin LUT
// ============================================================================
__global__ void rope_lut(const int* __restrict__ pos)
{
    int idx = blockIdx.x * 256 + threadIdx.x;   // 0 .. SEQ*64-1
    int s = idx >> 6;
    int j = idx & 63;                            // d = 2j
    float freq = (float)exp(-(double)(2 * j) * (9.210340371976184 / 128.0));
    float p = (float)pos[s];
    double ang = (double)(p * freq);
    double q   = rint(ang * 0.15915494309189535);
    float red  = (float)(ang - q * 6.283185307179586);
    float sn, cs;
    sincosf(red, &sn, &cs);
    g_rc[idx] = cs;
    g_rs[idx] = sn;
}

// ============================================================================
// fp16 mma.sync NT GEMM: C = A * B^T (A[M,K], B[N,K] row-major, half).
// CTA tile 256x128, BK=64 halves, 256 thr, 8 warps (4m x 2n), warp tile 64x64
// (4x8 m16n8k16 frags), fp32 accum, 2-stage cp.async.
// MODE 0: fused QKV (grid 48 x 16; wsel = x%3, head = x/3).
//   Q: scale+RoPE -> g_Q;  K: RoPE -> g_K;  V: transpose -> g_Vt.
// MODE 1: wo (grid 16 x 16), A = g_att, fp32 out -> Cout.
// ============================================================================
#define TSTR    72                       // halves per smem row (36 words)
#define ATILEH  (256 * TSTR)             // A: 18432 halves
#define BTILEH  (128 * TSTR)             // B:  9216 halves
#define STAGEH  (ATILEH + BTILEH)        // 27648 halves = 55296 B
#define GEMM_SMEM (2 * STAGEH * 2)       // 110592 B
#define QSCALE 0.08838834764831845f

template<int MODE>
__global__ __launch_bounds__(256, 1) void gemm_mma(float* __restrict__ Cout)
{
    extern __shared__ char smc[];
    __half* smh = (__half*)smc;
    const int tid = threadIdx.x;
    const int wid = tid >> 5;
    const int lane = tid & 31;
    const int g = lane >> 2;
    const int cl = lane & 3;
    const int wm = wid & 3;              // 0..3  (64 rows each)
    const int wn = wid >> 2;             // 0..1  (64 cols each)
    const int m0 = blockIdx.y * 256;

    int wsel, hh, n0;
    if (MODE == 0) { wsel = blockIdx.x % 3; hh = blockIdx.x / 3; n0 = hh * 128; }
    else           { wsel = 3; hh = 0; n0 = blockIdx.x * 128; }

    const __half* __restrict__ Ap = (MODE == 0) ? g_xh : g_att;
    const __half* __restrict__ Bp = (MODE == 1) ? g_woh :
                                    (wsel == 0) ? g_wqh :
                                    (wsel == 1) ? g_wkh : g_wvh;
    const __half* __restrict__ arow = Ap + (size_t)m0 * KDIM;
    const __half* __restrict__ brow = Bp + (size_t)n0 * KDIM;

    const uint32_t sb = smem_u32(smc);
    const int ldr = tid >> 3;            // 0..31
    const int ldc = (tid & 7) * 8;       // half offset 0..56

    auto load_tile = [&](int stage, int kt) {
        uint32_t base = sb + stage * STAGEH * 2;
        #pragma unroll
        for (int i = 0; i < 8; i++) {    // A: 256 rows
            int r = ldr + i * 32;
            CP16(base + (r * TSTR + ldc) * 2, &arow[(size_t)r * KDIM + kt + ldc]);
        }
        #pragma unroll
        for (int i = 0; i < 4; i++) {    // B: 128 rows
            int r = ldr + i * 32;
            CP16(base + (ATILEH + r * TSTR + ldc) * 2,
                 &brow[(size_t)r * KDIM + kt + ldc]);
        }
    };

    float acc[4][8][4];
    #pragma unroll
    for (int i = 0; i < 4; i++)
        #pragma unroll
        for (int j = 0; j < 8; j++)
            #pragma unroll
            for (int k = 0; k < 4; k++) acc[i][j][k] = 0.0f;

    load_tile(0, 0);
    CP_COMMIT();

    const int aoff0 = (wm * 64 + g) * 36 + cl;   // word units
    const int boff0 = (wn * 64 + g) * 36 + cl;

    for (int c = 0; c < 32; c++) {
        if (c + 1 < 32) {
            load_tile((c + 1) & 1, (c + 1) * 64);
            CP_COMMIT();
            CP_WAIT(1);
        } else {
            CP_WAIT(0);
        }
        __syncthreads();

        const uint32_t* As32 = (const uint32_t*)(smh + (c & 1) * STAGEH);
        const uint32_t* Bs32 = (const uint32_t*)(smh + (c & 1) * STAGEH + ATILEH);

        #pragma unroll
        for (int ks = 0; ks < 4; ks++) {
            uint32_t a[4][4], b[8][2];
            #pragma unroll
            for (int mf = 0; mf < 4; mf++) {
                int o = aoff0 + mf * 16 * 36 + ks * 8;
                a[mf][0] = As32[o];
                a[mf][1] = As32[o + 8 * 36];
                a[mf][2] = As32[o + 4];
                a[mf][3] = As32[o + 8 * 36 + 4];
            }
            #pragma unroll
            for (int nf = 0; nf < 8; nf++) {
                int o = boff0 + nf * 8 * 36 + ks * 8;
                b[nf][0] = Bs32[o];
                b[nf][1] = Bs32[o + 4];
            }
            #pragma unroll
            for (int mf = 0; mf < 4; mf++)
                #pragma unroll
                for (int nf = 0; nf < 8; nf++)
                    mma_f16(acc[mf][nf][0], acc[mf][nf][1],
                            acc[mf][nf][2], acc[mf][nf][3],
                            a[mf][0], a[mf][1], a[mf][2], a[mf][3],
                            b[nf][0], b[nf][1]);
        }
        __syncthreads();
    }

    // ---- epilogues ----
    if (MODE == 1) {
        #pragma unroll
        for (int mf = 0; mf < 4; mf++)
            #pragma unroll
            for (int half = 0; half < 2; half++) {
                int m = m0 + wm * 64 + mf * 16 + g + half * 8;
                float* o = &Cout[(size_t)m * D_MODEL + n0 + wn * 64 + cl * 2];
                #pragma unroll
                for (int nf = 0; nf < 8; nf++)
                    *(float2*)&o[nf * 8] =
                        make_float2(acc[mf][nf][half * 2], acc[mf][nf][half * 2 + 1]);
            }
        return;
    }

    if (wsel == 2) {
        // V: fp16, transpose through smem, write g_Vt[b,h,d,s] coalesced.
        __half* T = smh;                       // 128 d x 264 stride (67584 B)
        #pragma unroll
        for (int mf = 0; mf < 4; mf++)
            #pragma unroll
            for (int half = 0; half < 2; half++) {
                int sl = wm * 64 + mf * 16 + g + half * 8;      // 0..255
                #pragma unroll
                for (int nf = 0; nf < 8; nf++) {
                    int dl = wn * 64 + nf * 8 + cl * 2;          // 0..126 even
                    T[dl * 264 + sl]       = __float2half_rn(acc[mf][nf][half * 2]);
                    T[(dl + 1) * 264 + sl] = __float2half_rn(acc[mf][nf][half * 2 + 1]);
                }
            }
        __syncthreads();
        const int b = m0 >> 11;
        const int srow0 = m0 & 2047;
        #pragma unroll
        for (int i = 0; i < 16; i++) {
            int idx = tid + i * 256;
            int r   = idx >> 5;               // d row 0..127
            int c8  = (idx & 31) * 8;         // s col 0..248
            uint4 v = *(uint4*)&T[r * 264 + c8];
            *(uint4*)&g_Vt[((size_t)((b * NH + hh) * DK + r)) * SEQ + srow0 + c8] = v;
        }
        return;
    }

    // Q or K: (Q folds 1/sqrt(dk)), RoPE via LUT, store half [b,h,s,d]
    __half* dptr = (wsel == 0) ? g_Q : g_K;
    const float qs = (wsel == 0) ? QSCALE : 1.0f;
    #pragma unroll
    for (int mf = 0; mf < 4; mf++)
        #pragma unroll
        for (int half = 0; half < 2; half++) {
            int m = m0 + wm * 64 + mf * 16 + g + half * 8;
            int b = m >> 11;
            int s = m & 2047;
            const float* lc = &g_rc[s * 64 + wn * 32 + cl];
            const float* ls = &g_rs[s * 64 + wn * 32 + cl];
            __half2* o = (__half2*)&dptr[(size_t)((b * NH + hh) * SEQ + s) * DK
                                         + wn * 64 + cl * 2];
            #pragma unroll
            for (int nf = 0; nf < 8; nf++) {
                float cs = lc[nf * 4];
                float sn = ls[nf * 4];
                float e  = acc[mf][nf][half * 2] * qs;
                float od = acc[mf][nf][half * 2 + 1] * qs;
                o[nf * 4] = __floats2half2_rn(e * cs - od * sn, e * sn + od * cs);
            }
        }
}

// ============================================================================
// Flash attention (unchanged from R7): fp16 mma, fully cp.async.
// Q-tile 128 x kv-tile 64, 8 warps, warp w owns q rows [16w,16w+16).
// smem halves: Qs 128x136 | Ks 2x 64x136 | Vt 128x72 | Ps 128x72
// ============================================================================
#define FQ  0
#define FKo (128 * 136)
#define FKS (64 * 136)
#define FV  (FKo + 2 * FKS)
#define FP  (FV + 128 * 72)
#define FLASH_SMEM ((FP + 128 * 72) * 2)     // 106496 B
#define L2E 1.4426950408889634f

__global__ __launch_bounds__(256, 1) void flash_mma()
{
    extern __shared__ char smc[];
    __half* smh = (__half*)smc;
    const uint32_t sb = smem_u32(smc);

    const int tid  = threadIdx.x;
    const int w    = tid >> 5;
    const int lane = tid & 31;
    const int g    = lane >> 2;
    const int cl   = lane & 3;
    const int qt   = (gridDim.x - 1) - blockIdx.x;   // heavy tiles first
    const int bh   = blockIdx.y;
    const int q0   = qt * 128;
    const int wrow = w * 16;

    auto issue_Q = [&]() {
        #pragma unroll
        for (int i = 0; i < 8; i++) {
            int idx = tid + i * 256;
            int r = idx >> 4, c8 = (idx & 15) * 8;
            CP16(sb + (r * 136 + c8) * 2,
                 &g_Q[(size_t)(bh * SEQ + q0 + r) * DK + c8]);
        }
    };
    auto issue_K = [&](int kt) {
        int st = kt & 1, k0 = kt * 64;
        #pragma unroll
        for (int i = 0; i < 4; i++) {
            int idx = tid + i * 256;
            int r = idx >> 4, c8 = (idx & 15) * 8;
            CP16(sb + (FKo + st * FKS + r * 136 + c8) * 2,
                 &g_K[(size_t)(bh * SEQ + k0 + r) * DK + c8]);
        }
    };
    auto issue_V = [&](int kt) {
        int k0 = kt * 64;
        #pragma unroll
        for (int i = 0; i < 4; i++) {
            int idx = tid + i * 256;
            int d = idx >> 3, c8 = (idx & 7) * 8;
            CP16(sb + (FV + d * 72 + c8) * 2,
                 &g_Vt[((size_t)bh * DK + d) * SEQ + k0 + c8]);
        }
    };

    issue_K(0);
    issue_Q();
    CP_COMMIT();

    float oacc[16][4];
    #pragma unroll
    for (int i = 0; i < 16; i++)
        #pragma unroll
        for (int k = 0; k < 4; k++) oacc[i][k] = 0.0f;
    float mrow[2] = {-INFINITY, -INFINITY};
    float lrow[2] = {0.0f, 0.0f};

    const int ktiles = 2 * qt + 2;
    for (int kt = 0; kt < ktiles; kt++) {
        const int k0 = kt * 64;

        __syncthreads();             // prev tile fully consumed
        issue_V(kt); CP_COMMIT();
        if (kt + 1 < ktiles) { issue_K(kt + 1); CP_COMMIT(); CP_WAIT(2); }
        else                 { CP_WAIT(1); }
        __syncthreads();             // Q + Ks(kt) visible to all warps

        const uint32_t* Q32 = (const uint32_t*)smh;
        const uint32_t* K32 = (const uint32_t*)(smh + FKo + (kt & 1) * FKS);

        // ---- S = Q K^T ----
        float sacc[8][4];
        #pragma unroll
        for (int nf = 0; nf < 8; nf++)
            #pragma unroll
            for (int k = 0; k < 4; k++) sacc[nf][k] = 0.0f;

        #pragma unroll
        for (int ks = 0; ks < 8; ks++) {
            int ao = (wrow + g) * 68 + ks * 8 + cl;
            uint32_t a0 = Q32[ao];
            uint32_t a1 = Q32[ao + 8 * 68];
            uint32_t a2 = Q32[ao + 4];
            uint32_t a3 = Q32[ao + 8 * 68 + 4];
            #pragma unroll
            for (int nf = 0; nf < 8; nf++) {
                int bo = (nf * 8 + g) * 68 + ks * 8 + cl;
                uint32_t b0 = K32[bo];
                uint32_t b1 = K32[bo + 4];
                mma_f16(sacc[nf][0], sacc[nf][1], sacc[nf][2], sacc[nf][3],
                        a0, a1, a2, a3, b0, b1);
            }
        }

        // ---- causal mask ----
        if (k0 + 63 > q0 + wrow) {
            #pragma unroll
            for (int nf = 0; nf < 8; nf++)
                #pragma unroll
                for (int k = 0; k < 4; k++) {
                    int row = q0 + wrow + g + (k >> 1) * 8;
                    int col = k0 + nf * 8 + cl * 2 + (k & 1);
                    if (col > row) sacc[nf][k] = -INFINITY;
                }
        }

        // ---- online softmax (rows g, g+8) ----
        #pragma unroll
        for (int h = 0; h < 2; h++) {
            float mt = -INFINITY;
            #pragma unroll
            for (int nf = 0; nf < 8; nf++)
                mt = fmaxf(mt, fmaxf(sacc[nf][h * 2], sacc[nf][h * 2 + 1]));
            mt = fmaxf(mt, __shfl_xor_sync(0xffffffffu, mt, 1));
            mt = fmaxf(mt, __shfl_xor_sync(0xffffffffu, mt, 2));
            float mnew  = fmaxf(mrow[h], mt);
            float alpha = exp2f((mrow[h] - mnew) * L2E);
            float psum  = 0.0f;
            __half2* prow = (__half2*)(smh + FP + (wrow + g + h * 8) * 72) + cl;
            #pragma unroll
            for (int nf = 0; nf < 8; nf++) {
                float p0 = exp2f((sacc[nf][h * 2]     - mnew) * L2E);
                float p1 = exp2f((sacc[nf][h * 2 + 1] - mnew) * L2E);
                psum += p0 + p1;
                prow[nf * 4] = __floats2half2_rn(p0, p1);
            }
            psum += __shfl_xor_sync(0xffffffffu, psum, 1);
            psum += __shfl_xor_sync(0xffffffffu, psum, 2);
            lrow[h] = lrow[h] * alpha + psum;
            mrow[h] = mnew;
            #pragma unroll
            for (int nf2 = 0; nf2 < 16; nf2++) {
                oacc[nf2][h * 2]     *= alpha;
                oacc[nf2][h * 2 + 1] *= alpha;
            }
        }
        __syncwarp();                // Ps rows are warp-private; cross-lane only

        if (kt + 1 < ktiles) { CP_WAIT(1); }  // Vt(kt) done; K(kt+1) may pend
        else                 { CP_WAIT(0); }
        __syncthreads();             // Vt visible to all warps

        // ---- O += P * V ----
        const uint32_t* P32 = (const uint32_t*)(smh + FP);
        const uint32_t* V32 = (const uint32_t*)(smh + FV);
        #pragma unroll
        for (int ks = 0; ks < 4; ks++) {
            int ao = (wrow + g) * 36 + ks * 8 + cl;
            uint32_t a0 = P32[ao];
            uint32_t a1 = P32[ao + 8 * 36];
            uint32_t a2 = P32[ao + 4];
            uint32_t a3 = P32[ao + 8 * 36 + 4];
            #pragma unroll
            for (int nf2 = 0; nf2 < 16; nf2++) {
                int bo = (nf2 * 8 + g) * 36 + ks * 8 + cl;
                uint32_t b0 = V32[bo];
                uint32_t b1 = V32[bo + 4];
                mma_f16(oacc[nf2][0], oacc[nf2][1], oacc[nf2][2], oacc[nf2][3],
                        a0, a1, a2, a3, b0, b1);
            }
        }
    }

    // ---- epilogue: scale by 1/l, store half (feeds wo GEMM) ----
    const int b  = bh >> 4;
    const int hh = bh & 15;
    #pragma unroll
    for (int h = 0; h < 2; h++) {
        float inv = 1.0f / lrow[h];
        int row = q0 + wrow + g + h * 8;
        __half2* o = (__half2*)&g_att[(size_t)(b * SEQ + row) * D_MODEL
                                      + hh * DK + cl * 2];
        #pragma unroll
        for (int nf2 = 0; nf2 < 16; nf2++)
            o[nf2 * 4] = __floats2half2_rn(oacc[nf2][h * 2]     * inv,
                                           oacc[nf2][h * 2 + 1] * inv);
    }
}

// ============================================================================
extern "C" void kernel_launch(void* const* d_in, const int* in_sizes, int n_in,
                              void* d_out, int out_size)
{
    const float* x   = (const float*)d_in[0];
    const float* wq  = (const float*)d_in[1];
    const float* wk  = (const float*)d_in[2];
    const float* wv  = (const float*)d_in[3];
    const float* wo  = (const float*)d_in[4];
    const int*   pos = (const int*)  d_in[5];
    float* out = (float*)d_out;

    cudaFuncSetAttribute(gemm_mma<0>, cudaFuncAttributeMaxDynamicSharedMemorySize,
                         GEMM_SMEM);
    cudaFuncSetAttribute(gemm_mma<1>, cudaFuncAttributeMaxDynamicSharedMemorySize,
                         GEMM_SMEM);
    cudaFuncSetAttribute(flash_mma, cudaFuncAttributeMaxDynamicSharedMemorySize,
                         FLASH_SMEM);

    // (8M + 16M) elems / 8 per thread / 256 per block = 12288 blocks
    to_half_all<<<12288, 256>>>(x, wq, wk, wv, wo);
    rope_lut<<<(SEQ*64)/256, 256>>>(pos);

    gemm_mma<0><<<dim3(48, MDIM/256), 256, GEMM_SMEM>>>(nullptr);      // QKV
    flash_mma<<<dim3(SEQ/128, BATCH*NH), 256, FLASH_SMEM>>>();
    gemm_mma<1><<<dim3(D_MODEL/128, MDIM/256), 256, GEMM_SMEM>>>(out); // wo
}